// round 1
// baseline (speedup 1.0000x reference)
#include <cuda_runtime.h>

// dW[i,j] = sum_{a,b,c} coeffs[a,b,c] * x[j]^a * y[i]^b * w[i,j]^c
// N_POST = N_PRE = 8192, fp32.
//
// Factorization: r[a][c] = sum_b coeffs[a,b,c] * y[i]^b   (per row, 9 floats)
//                s_c(j)  = r[0][c] + x[j]*r[1][c] + x[j]^2*r[2][c]
//                dW      = s0 + w*(s1 + w*s2)
//
// Memory-bound streaming kernel: float4 in/out, 2 blocks per row,
// each block = 256 threads x 4 float4 iterations = 4096 columns.

#define N_PRE  8192
#define N_POST 8192
#define F4_PER_ROW (N_PRE / 4)          // 2048
#define THREADS 256
#define ITERS 4                         // float4 per thread
#define BLOCKS_PER_ROW (F4_PER_ROW / (THREADS * ITERS))  // 2

__global__ __launch_bounds__(THREADS)
void taylor3_kernel(const float* __restrict__ x,
                    const float* __restrict__ y,
                    const float4* __restrict__ w4,
                    const float* __restrict__ coeffs,
                    float4* __restrict__ out4)
{
    const int row      = blockIdx.x >> 1;          // BLOCKS_PER_ROW == 2
    const int colBlock = blockIdx.x & 1;

    const float yi = __ldg(&y[row]);
    const float y2 = yi * yi;

    // r[a][c] = coeffs[a,0,c] + yi*coeffs[a,1,c] + y2*coeffs[a,2,c]
    float r[3][3];
#pragma unroll
    for (int a = 0; a < 3; ++a) {
#pragma unroll
        for (int c = 0; c < 3; ++c) {
            const float c0 = __ldg(&coeffs[a * 9 + 0 * 3 + c]);
            const float c1 = __ldg(&coeffs[a * 9 + 1 * 3 + c]);
            const float c2 = __ldg(&coeffs[a * 9 + 2 * 3 + c]);
            r[a][c] = fmaf(y2, c2, fmaf(yi, c1, c0));
        }
    }

    // base float4 index within the row for this block
    const int colBase = colBlock * (THREADS * ITERS);   // 0 or 1024
    const long rowBase = (long)row * F4_PER_ROW;

    const float4* __restrict__ x4 = (const float4*)x;

#pragma unroll
    for (int it = 0; it < ITERS; ++it) {
        const int c4 = colBase + it * THREADS + threadIdx.x;  // float4 col index
        const float4 xv = __ldg(&x4[c4]);
        const float4 wv = __ldg(&w4[rowBase + c4]);

        float4 ov;
        {
            const float xj = xv.x, wj = wv.x, x2 = xj * xj;
            const float s0 = fmaf(x2, r[2][0], fmaf(xj, r[1][0], r[0][0]));
            const float s1 = fmaf(x2, r[2][1], fmaf(xj, r[1][1], r[0][1]));
            const float s2 = fmaf(x2, r[2][2], fmaf(xj, r[1][2], r[0][2]));
            ov.x = fmaf(wj, fmaf(wj, s2, s1), s0);
        }
        {
            const float xj = xv.y, wj = wv.y, x2 = xj * xj;
            const float s0 = fmaf(x2, r[2][0], fmaf(xj, r[1][0], r[0][0]));
            const float s1 = fmaf(x2, r[2][1], fmaf(xj, r[1][1], r[0][1]));
            const float s2 = fmaf(x2, r[2][2], fmaf(xj, r[1][2], r[0][2]));
            ov.y = fmaf(wj, fmaf(wj, s2, s1), s0);
        }
        {
            const float xj = xv.z, wj = wv.z, x2 = xj * xj;
            const float s0 = fmaf(x2, r[2][0], fmaf(xj, r[1][0], r[0][0]));
            const float s1 = fmaf(x2, r[2][1], fmaf(xj, r[1][1], r[0][1]));
            const float s2 = fmaf(x2, r[2][2], fmaf(xj, r[1][2], r[0][2]));
            ov.z = fmaf(wj, fmaf(wj, s2, s1), s0);
        }
        {
            const float xj = xv.w, wj = wv.w, x2 = xj * xj;
            const float s0 = fmaf(x2, r[2][0], fmaf(xj, r[1][0], r[0][0]));
            const float s1 = fmaf(x2, r[2][1], fmaf(xj, r[1][1], r[0][1]));
            const float s2 = fmaf(x2, r[2][2], fmaf(xj, r[1][2], r[0][2]));
            ov.w = fmaf(wj, fmaf(wj, s2, s1), s0);
        }

        out4[rowBase + c4] = ov;
    }
}

extern "C" void kernel_launch(void* const* d_in, const int* in_sizes, int n_in,
                              void* d_out, int out_size)
{
    const float* x      = (const float*)d_in[0];   // [8192]
    const float* y      = (const float*)d_in[1];   // [8192]
    const float* w      = (const float*)d_in[2];   // [8192, 8192]
    const float* coeffs = (const float*)d_in[3];   // [3,3,3]
    float* out          = (float*)d_out;           // [8192, 8192]

    const int blocks = N_POST * BLOCKS_PER_ROW;    // 16384
    taylor3_kernel<<<blocks, THREADS>>>(x, y, (const float4*)w, coeffs,
                                        (float4*)out);
}

// round 3
// speedup vs baseline: 1.1424x; 1.1424x over previous
#include <cuda_runtime.h>

// dW[i,j] = sum_{a,b,c} coeffs[a,b,c] * x[j]^a * y[i]^b * w[i,j]^c
// N_POST = N_PRE = 8192, fp32. Streaming kernel at the HBM roofline.
//
// r[a][c] = sum_b coeffs[a,b,c]*y[i]^b  (9 per-row floats)
// s_c     = r[0][c] + x*r[1][c] + x^2*r[2][c]
// dW      = s0 + w*(s1 + w*s2)
//
// One block per row: 256 threads x 8 iterations x float4 = 8192 columns.
// Cache policy: w streamed (__ldcs, evict-first), out streamed (__stcs),
// x cached (__ldg) so the 32KB x vector stays L2/L1-resident across rows.

#define N_PRE  8192
#define N_POST 8192
#define THREADS 256
#define ITERS 8                 // float4 groups per thread

__global__ __launch_bounds__(THREADS)
void taylor3_kernel(const float* __restrict__ x,
                    const float* __restrict__ y,
                    const float4* __restrict__ w4,
                    const float* __restrict__ coeffs,
                    float4* __restrict__ out4)
{
    const int row = blockIdx.x;

    const float yi = __ldg(&y[row]);
    const float y2 = yi * yi;

    // r[a][c] = coeffs[a,0,c] + yi*coeffs[a,1,c] + y2*coeffs[a,2,c]
    float r[3][3];
#pragma unroll
    for (int a = 0; a < 3; ++a) {
#pragma unroll
        for (int c = 0; c < 3; ++c) {
            const float c0 = __ldg(&coeffs[a * 9 + 0 + c]);
            const float c1 = __ldg(&coeffs[a * 9 + 3 + c]);
            const float c2 = __ldg(&coeffs[a * 9 + 6 + c]);
            r[a][c] = fmaf(y2, c2, fmaf(yi, c1, c0));
        }
    }

    const long rowBase = (long)row * (N_PRE / 4);
    const float4* __restrict__ x4 = (const float4*)x;

#pragma unroll
    for (int it = 0; it < ITERS; ++it) {
        const int c4 = it * THREADS + threadIdx.x;      // float4 col index
        const float4 xv = __ldg(&x4[c4]);
        const float4 wv = __ldcs(&w4[rowBase + c4]);    // streaming read

        float4 ov;
        {
            const float xj = xv.x, wj = wv.x, x2 = xj * xj;
            const float s0 = fmaf(x2, r[2][0], fmaf(xj, r[1][0], r[0][0]));
            const float s1 = fmaf(x2, r[2][1], fmaf(xj, r[1][1], r[0][1]));
            const float s2 = fmaf(x2, r[2][2], fmaf(xj, r[1][2], r[0][2]));
            ov.x = fmaf(wj, fmaf(wj, s2, s1), s0);
        }
        {
            const float xj = xv.y, wj = wv.y, x2 = xj * xj;
            const float s0 = fmaf(x2, r[2][0], fmaf(xj, r[1][0], r[0][0]));
            const float s1 = fmaf(x2, r[2][1], fmaf(xj, r[1][1], r[0][1]));
            const float s2 = fmaf(x2, r[2][2], fmaf(xj, r[1][2], r[0][2]));
            ov.y = fmaf(wj, fmaf(wj, s2, s1), s0);
        }
        {
            const float xj = xv.z, wj = wv.z, x2 = xj * xj;
            const float s0 = fmaf(x2, r[2][0], fmaf(xj, r[1][0], r[0][0]));
            const float s1 = fmaf(x2, r[2][1], fmaf(xj, r[1][1], r[0][1]));
            const float s2 = fmaf(x2, r[2][2], fmaf(xj, r[1][2], r[0][2]));
            ov.z = fmaf(wj, fmaf(wj, s2, s1), s0);
        }
        {
            const float xj = xv.w, wj = wv.w, x2 = xj * xj;
            const float s0 = fmaf(x2, r[2][0], fmaf(xj, r[1][0], r[0][0]));
            const float s1 = fmaf(x2, r[2][1], fmaf(xj, r[1][1], r[0][1]));
            const float s2 = fmaf(x2, r[2][2], fmaf(xj, r[1][2], r[0][2]));
            ov.w = fmaf(wj, fmaf(wj, s2, s1), s0);
        }

        __stcs(&out4[rowBase + c4], ov);                // streaming store
    }
}

extern "C" void kernel_launch(void* const* d_in, const int* in_sizes, int n_in,
                              void* d_out, int out_size)
{
    const float* x      = (const float*)d_in[0];   // [8192]
    const float* y      = (const float*)d_in[1];   // [8192]
    const float* w      = (const float*)d_in[2];   // [8192, 8192]
    const float* coeffs = (const float*)d_in[3];   // [3,3,3]
    float* out          = (float*)d_out;           // [8192, 8192]

    taylor3_kernel<<<N_POST, THREADS>>>(x, y, (const float4*)w, coeffs,
                                        (float4*)out);
}

// round 4
// speedup vs baseline: 1.1429x; 1.0004x over previous
#include <cuda_runtime.h>

// dW[i,j] = sum_{a,b,c} coeffs[a,b,c] * x[j]^a * y[i]^b * w[i,j]^c
// N_POST = N_PRE = 8192, fp32. Streaming kernel at the HBM roofline.
//
// r[a][c] = sum_b coeffs[a,b,c]*y[i]^b  (9 per-row floats)
// s_c     = r[0][c] + x*r[1][c] + x^2*r[2][c]
// dW      = s0 + w*(s1 + w*s2)
//
// One block per row: 256 threads x 8 iterations x float4 = 8192 columns.
// Cache policy: w streamed (__ldcs), out streamed (__stcs), x cached (__ldg).
// Two-deep software pipeline: iteration k+1's loads are issued before
// iteration k's compute+store, coarsening read/write bursts to reduce
// HBM bus turnaround.

#define N_PRE  8192
#define N_POST 8192
#define THREADS 256
#define ITERS 8                 // float4 groups per thread

__device__ __forceinline__ float4 poly4(const float4 xv, const float4 wv,
                                        const float r[3][3])
{
    float4 ov;
#pragma unroll
    for (int e = 0; e < 4; ++e) {
        const float xj = (&xv.x)[e];
        const float wj = (&wv.x)[e];
        const float x2 = xj * xj;
        const float s0 = fmaf(x2, r[2][0], fmaf(xj, r[1][0], r[0][0]));
        const float s1 = fmaf(x2, r[2][1], fmaf(xj, r[1][1], r[0][1]));
        const float s2 = fmaf(x2, r[2][2], fmaf(xj, r[1][2], r[0][2]));
        (&ov.x)[e] = fmaf(wj, fmaf(wj, s2, s1), s0);
    }
    return ov;
}

__global__ __launch_bounds__(THREADS)
void taylor3_kernel(const float* __restrict__ x,
                    const float* __restrict__ y,
                    const float4* __restrict__ w4,
                    const float* __restrict__ coeffs,
                    float4* __restrict__ out4)
{
    const int row = blockIdx.x;

    const float yi = __ldg(&y[row]);
    const float y2 = yi * yi;

    float r[3][3];
#pragma unroll
    for (int a = 0; a < 3; ++a) {
#pragma unroll
        for (int c = 0; c < 3; ++c) {
            const float c0 = __ldg(&coeffs[a * 9 + 0 + c]);
            const float c1 = __ldg(&coeffs[a * 9 + 3 + c]);
            const float c2 = __ldg(&coeffs[a * 9 + 6 + c]);
            r[a][c] = fmaf(y2, c2, fmaf(yi, c1, c0));
        }
    }

    const long rowBase = (long)row * (N_PRE / 4);
    const float4* __restrict__ x4 = (const float4*)x;

    // Two-deep pipeline: prefetch next iteration's loads before current store.
    int c4 = threadIdx.x;
    float4 xv_cur = __ldg(&x4[c4]);
    float4 wv_cur = __ldcs(&w4[rowBase + c4]);

#pragma unroll
    for (int it = 0; it < ITERS - 1; ++it) {
        const int c4n = c4 + THREADS;
        // issue next loads first (front-batch the read burst)
        const float4 xv_nxt = __ldg(&x4[c4n]);
        const float4 wv_nxt = __ldcs(&w4[rowBase + c4n]);

        const float4 ov = poly4(xv_cur, wv_cur, r);
        __stcs(&out4[rowBase + c4], ov);

        xv_cur = xv_nxt;
        wv_cur = wv_nxt;
        c4 = c4n;
    }

    // epilogue
    const float4 ov = poly4(xv_cur, wv_cur, r);
    __stcs(&out4[rowBase + c4], ov);
}

extern "C" void kernel_launch(void* const* d_in, const int* in_sizes, int n_in,
                              void* d_out, int out_size)
{
    const float* x      = (const float*)d_in[0];   // [8192]
    const float* y      = (const float*)d_in[1];   // [8192]
    const float* w      = (const float*)d_in[2];   // [8192, 8192]
    const float* coeffs = (const float*)d_in[3];   // [3,3,3]
    float* out          = (float*)d_out;           // [8192, 8192]

    taylor3_kernel<<<N_POST, THREADS>>>(x, y, (const float4*)w, coeffs,
                                        (float4*)out);
}